// round 5
// baseline (speedup 1.0000x reference)
#include <cuda_runtime.h>

// RoiPooling: torchvision roi_pool (max), OUT=7x7, SCALE=0.125
// input:  (4, 256, 100, 152) fp32 NCHW
// boxes:  (K, 5) fp32  [batch_idx, x1, y1, x2, y2] image coords
// output: (K, 256, 7, 7) fp32
//
// SEMANTIC (verified R4): XLA rewrites (x / 7.0f) -> x * (1/7.0f); bin sizes
// MUST be computed as __fmul_rn(x, 1.0f/7.0f) to bit-match the reference.
//
// Layout: one CTA (256 thr) per ROI. Channels in chunks of 8: stage the ROI
// window into smem with coalesced row loads, compute 8x49 bin maxes from
// smem, write coalesced.

static constexpr int C_   = 256;
static constexpr int H_   = 100;
static constexpr int W_   = 152;
static constexpr int HW_  = H_ * W_;
static constexpr int CH_  = 8;                 // channels per chunk
static constexpr int WCAP = 26 * 26;           // max window cells (<=676)
static constexpr int WPAD = WCAP + 1;          // 677: break bank alignment

__global__ __launch_bounds__(256)
void roi_pool_staged(const float* __restrict__ x,
                     const float* __restrict__ boxes,
                     float* __restrict__ out)
{
    __shared__ float swin[CH_][WPAD];          // 8*677*4 = 21.7 KB
    __shared__ int   sbnd[4][7];               // hs, he, ws, we

    const int k    = blockIdx.x;
    const int tid  = threadIdx.x;
    const int wid  = tid >> 5;
    const int lane = tid & 31;

    // ---- per-ROI quantization + bin boundaries (once per block) ----
    const float* bx = boxes + (size_t)k * 5;
    const int b  = (int)bx[0];
    const int x1 = __float2int_rn(__fmul_rn(bx[1], 0.125f));
    const int y1 = __float2int_rn(__fmul_rn(bx[2], 0.125f));
    const int x2 = __float2int_rn(__fmul_rn(bx[3], 0.125f));
    const int y2 = __float2int_rn(__fmul_rn(bx[4], 0.125f));
    const int roi_w = max(x2 - x1 + 1, 1);
    const int roi_h = max(y2 - y1 + 1, 1);
    const float RCP7 = 1.0f / 7.0f;            // XLA reciprocal rewrite
    const float bin_h = __fmul_rn((float)roi_h, RCP7);
    const float bin_w = __fmul_rn((float)roi_w, RCP7);

    if (tid < 14) {
        const int p  = (tid < 7) ? tid : (tid - 7);
        const float pf = (float)p;
        if (tid < 7) {
            sbnd[0][p] = min(max((int)floorf(__fmul_rn(pf, bin_h)) + y1, 0), H_);
            sbnd[1][p] = min(max((int)ceilf(__fmul_rn(pf + 1.0f, bin_h)) + y1, 0), H_);
        } else {
            sbnd[2][p] = min(max((int)floorf(__fmul_rn(pf, bin_w)) + x1, 0), W_);
            sbnd[3][p] = min(max((int)ceilf(__fmul_rn(pf + 1.0f, bin_w)) + x1, 0), W_);
        }
    }
    __syncthreads();

    const int h0 = sbnd[0][0];
    const int h1 = sbnd[1][6];
    const int w0 = sbnd[2][0];
    const int w1 = sbnd[3][6];
    const int wh = max(h1 - h0, 0);
    const int ww = max(w1 - w0, 0);

    const float* src0 = x   + (size_t)b * C_ * HW_;
    float*       dst0 = out + (size_t)k * C_ * 49;

    const float NEG_INF = __int_as_float(0xff800000);

    for (int cb = 0; cb < C_; cb += CH_) {
        // ---- stage: warp per window row, coalesced, no integer divides ----
        #pragma unroll
        for (int ch = 0; ch < CH_; ++ch) {
            const float* pl = src0 + (size_t)(cb + ch) * HW_ + h0 * W_ + w0;
            for (int rr = wid; rr < wh; rr += 8) {
                const float* prow = pl + rr * W_;
                float*       srow = &swin[ch][rr * ww];
                for (int c = lane; c < ww; c += 32)
                    srow[c] = __ldg(prow + c);
            }
        }
        __syncthreads();

        // ---- compute: 8 ch x 49 bins, coalesced output writes ----
        for (int i = tid; i < CH_ * 49; i += 256) {
            const int ch  = i / 49;
            const int bin = i - ch * 49;
            const int ph  = bin / 7;
            const int pw  = bin - ph * 7;
            const int hs = sbnd[0][ph], he = sbnd[1][ph];
            const int ws = sbnd[2][pw], we = sbnd[3][pw];

            float m = NEG_INF;
            for (int r = hs; r < he; ++r) {
                const float* srow = &swin[ch][(r - h0) * ww - w0];
                for (int c = ws; c < we; ++c)
                    m = fmaxf(m, srow[c]);
            }
            const bool empty = (he <= hs) || (we <= ws);
            dst0[(cb + ch) * 49 + bin] = empty ? 0.0f : m;
        }
        __syncthreads();   // swin reuse guard
    }
}

extern "C" void kernel_launch(void* const* d_in, const int* in_sizes, int n_in,
                              void* d_out, int out_size) {
    const float* x     = (const float*)d_in[0];
    const float* boxes = (const float*)d_in[1];
    float*       out   = (float*)d_out;
    const int K = in_sizes[1] / 5;             // boxes is (K, 5)
    roi_pool_staged<<<K, 256>>>(x, boxes, out);
}

// round 6
// speedup vs baseline: 3.9714x; 3.9714x over previous
#include <cuda_runtime.h>

// RoiPooling: torchvision roi_pool (max), OUT=7x7, SCALE=0.125
// input:  (4, 256, 100, 152) fp32 NCHW
// boxes:  (K, 5) fp32  [batch_idx, x1, y1, x2, y2] image coords
// output: (K, 256, 7, 7) fp32
//
// SEMANTIC (verified R4): XLA rewrites (x / 7.0f) -> x * (1/7.0f); bin sizes
// MUST be computed as __fmul_rn(x, 1.0f/7.0f) to bit-match the reference.
//
// Two-phase: prep kernel computes per-(roi,bin) packed bounds + per-roi plane
// base once; main kernel is a thin max-gather with one thread per output.

static constexpr int C_   = 256;
static constexpr int H_   = 100;
static constexpr int W_   = 152;
static constexpr int HW_  = H_ * W_;
static constexpr int KMAX = 8192;

__device__ unsigned int g_bounds[KMAX * 49];  // hs|he<<8|ws<<16|we<<24
__device__ int          g_base[KMAX];         // b * C_ * HW_

__global__ __launch_bounds__(256)
void roi_prep(const float* __restrict__ boxes, int kb_total)
{
    const int i = blockIdx.x * blockDim.x + threadIdx.x;
    if (i >= kb_total) return;
    const int bin = i % 49;
    const int k   = i / 49;
    const int pw  = bin % 7;
    const int ph  = bin / 7;

    const float* bx = boxes + (size_t)k * 5;
    const int b  = (int)bx[0];
    const int x1 = __float2int_rn(__fmul_rn(bx[1], 0.125f));
    const int y1 = __float2int_rn(__fmul_rn(bx[2], 0.125f));
    const int x2 = __float2int_rn(__fmul_rn(bx[3], 0.125f));
    const int y2 = __float2int_rn(__fmul_rn(bx[4], 0.125f));
    const int roi_w = max(x2 - x1 + 1, 1);
    const int roi_h = max(y2 - y1 + 1, 1);
    const float RCP7 = 1.0f / 7.0f;           // XLA reciprocal rewrite
    const float bin_h = __fmul_rn((float)roi_h, RCP7);
    const float bin_w = __fmul_rn((float)roi_w, RCP7);

    const int hs = min(max((int)floorf(__fmul_rn((float)ph,       bin_h)) + y1, 0), H_);
    const int he = min(max((int)ceilf (__fmul_rn((float)(ph + 1), bin_h)) + y1, 0), H_);
    const int ws = min(max((int)floorf(__fmul_rn((float)pw,       bin_w)) + x1, 0), W_);
    const int we = min(max((int)ceilf (__fmul_rn((float)(pw + 1), bin_w)) + x1, 0), W_);

    g_bounds[i] = (unsigned)hs | ((unsigned)he << 8)
                | ((unsigned)ws << 16) | ((unsigned)we << 24);
    if (bin == 0) g_base[k] = b * C_ * HW_;
}

__global__ __launch_bounds__(256)
void roi_pool_main(const float* __restrict__ x,
                   float* __restrict__ out,
                   int total)
{
    const int o = blockIdx.x * blockDim.x + threadIdx.x;
    if (o >= total) return;

    const int bin = o % 49;
    const int c   = (o / 49) % C_;
    const int k   = o / (49 * C_);

    const unsigned w32 = g_bounds[k * 49 + bin];   // coalesced/broadcast
    const int hs =  w32        & 0xff;
    const int he = (w32 >> 8)  & 0xff;
    const int ws = (w32 >> 16) & 0xff;
    const int we = (w32 >> 24) & 0xff;

    const float* p = x + g_base[k] + c * HW_;

    float m = __int_as_float(0xff800000);          // -inf
    for (int r = hs; r < he; ++r) {
        const float* row = p + r * W_;
        for (int cc = ws; cc < we; ++cc)
            m = fmaxf(m, __ldg(row + cc));
    }

    const bool empty = (he <= hs) || (we <= ws);
    out[o] = empty ? 0.0f : m;
}

extern "C" void kernel_launch(void* const* d_in, const int* in_sizes, int n_in,
                              void* d_out, int out_size) {
    const float* x     = (const float*)d_in[0];
    const float* boxes = (const float*)d_in[1];
    float*       out   = (float*)d_out;
    const int K = in_sizes[1] / 5;                 // boxes is (K, 5)

    const int kb_total = K * 49;
    roi_prep<<<(kb_total + 255) / 256, 256>>>(boxes, kb_total);

    const int total = out_size;                    // K * 256 * 49
    roi_pool_main<<<(total + 255) / 256, 256>>>(x, out, total);
}